// round 12
// baseline (speedup 1.0000x reference)
#include <cuda_runtime.h>
#include <cuda_bf16.h>
#include <math.h>
#include <cstdint>

#define NQ   24576        // R*S
#define SS   48
#define MP   4096
#define LDX  512          // padded feature stride (D0=511 + 1 zero col)
#define D0   511
#define HD   256

// ---------------- scratch (static device globals; no runtime alloc) ----------
__device__ float g_X [NQ * LDX];   // 50 MB feature matrix (fp32)
__device__ float g_h1[NQ * HD];
__device__ float g_h2[NQ * HD];
// pre-split weights (bf16 hi/lo), W0 padded K 511 -> 512
__device__ __nv_bfloat16 g_w0h[HD * 512], g_w0l[HD * 512];
__device__ __nv_bfloat16 g_w1h[HD * HD],  g_w1l[HD * HD];
__device__ __nv_bfloat16 g_w2h[HD * HD],  g_w2l[HD * HD];
// spatial grid
__device__ int    g_start[1001];
__device__ float4 g_sorted[MP];    // cell-ordered particles, .w = index bits

// ============================ helpers ========================================
__device__ __forceinline__ uint32_t smem_u32(const void* p) {
    uint32_t a;
    asm("{ .reg .u64 t; cvta.to.shared.u64 t, %1; cvt.u32.u64 %0, t; }"
        : "=r"(a) : "l"(p));
    return a;
}
__device__ __forceinline__ void ldm_x4(uint32_t* r, uint32_t addr) {
    asm volatile("ldmatrix.sync.aligned.m8n8.x4.shared.b16 {%0,%1,%2,%3}, [%4];"
        : "=r"(r[0]), "=r"(r[1]), "=r"(r[2]), "=r"(r[3]) : "r"(addr));
}
__device__ __forceinline__ void mma_bf16(float* d, const uint32_t* a, const uint32_t* b) {
    asm volatile("mma.sync.aligned.m16n8k16.row.col.f32.bf16.bf16.f32 "
        "{%0,%1,%2,%3}, {%4,%5,%6,%7}, {%8,%9}, {%0,%1,%2,%3};"
        : "+f"(d[0]), "+f"(d[1]), "+f"(d[2]), "+f"(d[3])
        : "r"(a[0]), "r"(a[1]), "r"(a[2]), "r"(a[3]), "r"(b[0]), "r"(b[1]));
}
#define CP16(dst, src) \
    asm volatile("cp.async.cg.shared.global [%0], [%1], 16;" :: "r"(dst), "l"(src) : "memory")
#define CP_COMMIT() asm volatile("cp.async.commit_group;" ::: "memory")
#define CP_WAIT1()  asm volatile("cp.async.wait_group 1;" ::: "memory")

__device__ __forceinline__ uint32_t swz(uint32_t off) {
    return off ^ ((off >> 3) & 0x70);
}
__device__ __forceinline__ int cell_of(float x, float y, float z) {
    int cx = min(max(__float2int_rd(x * 10.0f), 0), 9);
    int cy = min(max(__float2int_rd(y * 10.0f), 0), 9);
    int cz = min(max(__float2int_rd(z * 10.0f), 0), 9);
    return cx + 10 * cy + 100 * cz;
}

// ---------------- grid build: ONE CTA does count + scan + scatter --------------
__global__ void __launch_bounds__(1024)
gridbuild_kernel(const float* __restrict__ pp)
{
    __shared__ int scnt[1000];
    __shared__ int ssc[1024];
    const int t = threadIdx.x;
    if (t < 1000) scnt[t] = 0;
    __syncthreads();
    for (int i = t; i < MP; i += 1024)
        atomicAdd(&scnt[cell_of(pp[3*i], pp[3*i+1], pp[3*i+2])], 1);
    __syncthreads();
    int v = (t < 1000) ? scnt[t] : 0;
    ssc[t] = v;
    __syncthreads();
    for (int d = 1; d < 1024; d <<= 1) {
        int u = (t >= d) ? ssc[t - d] : 0;
        __syncthreads();
        ssc[t] += u;
        __syncthreads();
    }
    if (t < 1000) { g_start[t] = ssc[t] - v; scnt[t] = ssc[t] - v; }
    if (t == 0)   g_start[1000] = MP;
    __syncthreads();
    for (int i = t; i < MP; i += 1024) {
        float x = pp[3*i], y = pp[3*i+1], z = pp[3*i+2];
        int c = cell_of(x, y, z);
        int pos = atomicAdd(&scnt[c], 1);
        g_sorted[pos] = make_float4(x, y, z, __int_as_float(i));
    }
}

// ---------------- posenc via double-angle recurrence (writes to smem row) ------
template<int C, int F>
__device__ __forceinline__ void posenc_write(float* dst, const float* v)
{
    float s[C], c[C];
    #pragma unroll
    for (int i = 0; i < C; i++) { dst[i] = v[i]; sincosf(v[i], &s[i], &c[i]); }
    #pragma unroll
    for (int f = 0; f < F; f++) {
        #pragma unroll
        for (int i = 0; i < C; i++) {
            dst[C + f*2*C + i]     = s[i];
            dst[C + f*2*C + C + i] = c[i];
        }
        if (f + 1 < F) {
            #pragma unroll
            for (int i = 0; i < C; i++) {
                float ns = 2.0f * s[i] * c[i];
                float nc = fmaf(-2.0f * s[i], s[i], 1.0f);
                s[i] = ns; c[i] = nc;
            }
        }
    }
}

// ---------------- feature kernel: grid ball query + embeddings + fv copy -------
// dyn smem: spts float4[4096] (64KB) | sstart int[1001] | SB float[128][SBW]
// SBW=261 (odd, 261 mod 32 = 5) -> per-lane banks 5*tid%32: conflict-free.
#define SBW      261
#define OF_START 65536
#define OF_SB    (OF_START + 4016)
#define FSMEM    (OF_SB + 128 * SBW * 4)

__global__ void __launch_bounds__(128)
feature_kernel(const float* __restrict__ points,
               const float* __restrict__ normals,
               const float* __restrict__ rays,
               const float* __restrict__ ro,
               const float* __restrict__ fv)
{
    extern __shared__ char fsm[];
    float4* spts   = (float4*)fsm;
    int*    sstart = (int*)(fsm + OF_START);
    float*  SBb    = (float*)(fsm + OF_SB);

    const int tid = threadIdx.x;
    for (int i = tid; i < MP;   i += 128) spts[i]   = g_sorted[i];
    for (int i = tid; i < 1001; i += 128) sstart[i] = g_start[i];
    __syncthreads();

    const int gid = blockIdx.x * 128 + tid;
    const float qx = points[3*gid+0], qy = points[3*gid+1], qz = points[3*gid+2];

    const float R2  = (float)(0.1 * 0.1);   // fp64-computed threshold bits
    const float RAD = 0.1f;

    int cand[64];
    int cnt = 0;
    {
        int cx = min(max(__float2int_rd(qx * 10.0f), 0), 9);
        int cy = min(max(__float2int_rd(qy * 10.0f), 0), 9);
        int cz = min(max(__float2int_rd(qz * 10.0f), 0), 9);
        int x0 = max(cx-1,0), x1 = min(cx+1,9);
        int y0 = max(cy-1,0), y1 = min(cy+1,9);
        int z0 = max(cz-1,0), z1 = min(cz+1,9);
        for (int zz = z0; zz <= z1; zz++)
        for (int yy = y0; yy <= y1; yy++)
        for (int xx = x0; xx <= x1; xx++) {
            int c  = xx + 10*yy + 100*zz;
            int s0 = sstart[c], s1 = sstart[c+1];
            for (int i = s0; i < s1; i++) {
                float4 p = spts[i];
                float dx = p.x - qx, dy = p.y - qy, dz = p.z - qz;
                float d2 = dx*dx + dy*dy + dz*dz;
                if (d2 < R2 && cnt < 64)
                    cand[cnt++] = (__float_as_int(p.w) << 12) | i;
            }
        }
    }
    // sort ascending by original index -> first-k-by-index semantics
    for (int i = 1; i < cnt; i++) {
        int v = cand[i], j = i - 1;
        while (j >= 0 && cand[j] > v) { cand[j+1] = cand[j]; j--; }
        cand[j+1] = v;
    }
    const int kk = min(cnt, 16);
    float nx[16], ny[16], nz[16], nd[16];
    for (int k = 0; k < kk; k++) {
        float4 p = spts[cand[k] & 4095];
        float dx = p.x - qx, dy = p.y - qy, dz = p.z - qz;
        nx[k] = p.x; ny[k] = p.y; nz[k] = p.z;
        nd[k] = dx*dx + dy*dy + dz*dz;
    }

    float qn = sqrtf(qx*qx + qy*qy + qz*qz);
    float t0 = qn / RAD;
    float w0 = fmaxf(1.0f - t0*t0*t0, 0.0f);

    float density = 0.0f, smx = 0.0f, smy = 0.0f, smz = 0.0f;
    for (int k = 0; k < 16; k++) {
        if (k < kk) {
            float dn = sqrtf(nd[k]);
            float tt = dn / RAD;
            float w  = fmaxf(1.0f - tt*tt*tt, 0.0f);
            density += w;
            smx += w * nx[k]; smy += w * ny[k]; smz += w * nz[k];
        } else {
            density += w0;
        }
    }

    int   num_nn = 0;
    float sdx = 0.0f, sdy = 0.0f, sdz = 0.0f;
    for (int k = 0; k < kk; k++) {
        if (nd[k] != 0.0f) {
            num_nn++;
            sdx += nx[k] - qx; sdy += ny[k] - qy; sdz += nz[k] - qz;
        }
    }
    float inv = (float)num_nn + 1e-12f;
    float mx = sdx / inv, my = sdy / inv, mz = sdz / inv;
    float vx = 0.0f, vy = 0.0f, vz = 0.0f;
    for (int k = 0; k < kk; k++) {
        if (nd[k] != 0.0f) {
            float ex = (nx[k] - qx) - mx;
            float ey = (ny[k] - qy) - my;
            float ez = (nz[k] - qz) - mz;
            vx += ex*ex; vy += ey*ey; vz += ez*ez;
        }
    }
    vx /= inv; vy /= inv; vz /= inv;

    float dinv = density + 1e-12f;
    float spx = smx / dinv, spy = smy / dinv, spz = smz / dinv;
    float dirx = spx - ro[0], diry = spy - ro[1], dirz = spz - ro[2];
    float dl = sqrtf(dirx*dirx + diry*diry + dirz*dirz);
    dirx /= dl; diry /= dl; dirz /= dl;

    // ---- build the row DIRECTLY in smem (no local-memory rowbuf) ----
    float* row = SBb + tid * SBW;
    float q3[3]  = {qx, qy, qz};       posenc_write<3,10>(row + 0,   q3);
    float d1[1]  = {density};          posenc_write<1,4> (row + 63,  d1);
    float sp3[3] = {spx, spy, spz};    posenc_write<3,10>(row + 72,  sp3);
    float v3[3]  = {vx, vy, vz};       posenc_write<3,10>(row + 135, v3);
    int r = gid / SS;
    float rd[3]  = {rays[6*r+3], rays[6*r+4], rays[6*r+5]};
    posenc_write<3,4>(row + 198, rd);
    float dd[3]  = {dirx, diry, dirz}; posenc_write<3,4> (row + 225, dd);
    row[252] = normals[3*gid+0];
    row[253] = normals[3*gid+1];
    row[254] = normals[3*gid+2];
    row[255] = 0.0f;   // col 255 placeholder (fv copy below overwrites)

    // ---- coalesced flush: smem -> global (one pass, 256 cols) ----
    const int rowGlobalBase = blockIdx.x * 128;
    __syncthreads();
    for (int i = tid; i < 128 * 256; i += 128) {
        int rr = i >> 8, cc = i & 255;
        g_X[(size_t)(rowGlobalBase + rr) * LDX + cc] = SBb[rr * SBW + cc];
    }

    // ---- fused fv copy: X[:,255:511] = fv (coalesced both sides) ----
    const float* fvb = fv + (size_t)rowGlobalBase * 256;
    float* Xb = g_X + (size_t)rowGlobalBase * LDX;
    for (int i = tid; i < 128 * 256; i += 128) {
        int rr = i >> 8, cc = i & 255;
        Xb[(size_t)rr * LDX + 255 + cc] = fvb[i];
    }
    Xb[(size_t)tid * LDX + 511] = 0.0f;   // pad column
}

// ---------------- weight split: fp32 -> bf16 hi/lo, K padded to Kp -------------
__global__ void __launch_bounds__(256)
convW_kernel(const float* __restrict__ W, int N, int K, int Kp,
             __nv_bfloat16* __restrict__ Wh, __nv_bfloat16* __restrict__ Wl)
{
    int i = blockIdx.x * 256 + threadIdx.x;
    if (i >= N * Kp) return;
    int n = i / Kp, k = i - n * Kp;
    float v = (k < K) ? W[(size_t)n * K + k] : 0.0f;
    __nv_bfloat16 h = __float2bfloat16(v);
    float r = v - __bfloat162float(h);
    Wh[i] = h;
    Wl[i] = __float2bfloat16(r);
}

// ================= warp-mma split-bf16 GEMM (round-9 version, verbatim) =======
// A fp32 converted in-kernel (post-compute staging, double buffer);
// B bf16 presplit via cp.async (triple buffer). Block 128m x 128n x 32k,
// 8 warps (4m x 2n), packed B ldm_x4 fragments. 2 CTAs/SM, regs=128 measured.
#define BM 128
#define BN 128
#define OFF_A0   0
#define OFF_A1   16384
#define OFF_B    32768            // B0,B1,B2 at +0, +16384, +32768
#define OFF_BIAS 81920
#define GSMEM    (OFF_BIAS + 512)

__device__ __forceinline__ void cvt8_bf16(const float* a, uint4& hv, uint4& lv)
{
    uint32_t hw[4], lw[4];
    #pragma unroll
    for (int e = 0; e < 4; e++) {
        __nv_bfloat16 h0 = __float2bfloat16(a[2*e]);
        __nv_bfloat16 h1 = __float2bfloat16(a[2*e+1]);
        float r0 = a[2*e]   - __bfloat162float(h0);
        float r1 = a[2*e+1] - __bfloat162float(h1);
        __nv_bfloat16 l0 = __float2bfloat16(r0);
        __nv_bfloat16 l1 = __float2bfloat16(r1);
        hw[e] = (uint32_t)__bfloat16_as_ushort(h0) | ((uint32_t)__bfloat16_as_ushort(h1) << 16);
        lw[e] = (uint32_t)__bfloat16_as_ushort(l0) | ((uint32_t)__bfloat16_as_ushort(l1) << 16);
    }
    hv = make_uint4(hw[0], hw[1], hw[2], hw[3]);
    lv = make_uint4(lw[0], lw[1], lw[2], lw[3]);
}

// A tile: fp32 gmem -> bf16 hi/lo -> smem (direct stores)
__device__ __forceinline__ void stage_A(char* dst, const float* __restrict__ A,
                                        int lda, int rowBase, int k0, int tid)
{
    const int arow = tid >> 2, acp = tid & 3;
    #pragma unroll
    for (int i = 0; i < 2; i++) {
        int row = arow + i * 64;
        const float* s = A + (size_t)(rowBase + row) * lda + k0 + acp * 8;
        float av[8];
        *(float4*)&av[0] = *(const float4*)s;
        *(float4*)&av[4] = *(const float4*)(s + 4);
        uint4 hv, lv; cvt8_bf16(av, hv, lv);
        uint32_t off = (uint32_t)(row << 7) + (uint32_t)(acp << 4);
        *(uint4*)(dst + swz(off))      = hv;
        *(uint4*)(dst + swz(off + 64)) = lv;
    }
}

// B tile: presplit bf16 -> smem via cp.async (16 KB)
__device__ __forceinline__ void stage_B(uint32_t dst,
                                        const __nv_bfloat16* __restrict__ Bh,
                                        const __nv_bfloat16* __restrict__ Bl,
                                        int ldb, int colBase, int k0, int tid)
{
    #pragma unroll
    for (int i = 0; i < 4; i++) {
        int u = tid + i * 256;
        int r = u >> 3, cu = u & 7;
        const __nv_bfloat16* src = (cu < 4)
            ? Bh + (size_t)(colBase + r) * ldb + k0 + cu * 8
            : Bl + (size_t)(colBase + r) * ldb + k0 + (cu - 4) * 8;
        CP16(dst + swz((uint32_t)(r << 7) + (uint32_t)(cu << 4)), src);
    }
}

__global__ void __launch_bounds__(256, 2)
mma_gemm_kernel(const float* __restrict__ A, int lda,
                const __nv_bfloat16* __restrict__ Bh,
                const __nv_bfloat16* __restrict__ Bl,
                int Kp,
                const float* __restrict__ bias,
                float* __restrict__ C)
{
    extern __shared__ char gsm[];
    const uint32_t sbase = smem_u32(gsm);
    float* sbias = (float*)(gsm + OFF_BIAS);

    const int tid  = threadIdx.x;
    const int wid  = tid >> 5;
    const int lane = tid & 31;
    const int wm   = wid & 3;          // 4 warps in m
    const int wn   = wid >> 2;         // 2 warps in n
    const int rowBase = blockIdx.x * BM;
    const int colBase = blockIdx.y * BN;

    if (tid < 128) sbias[tid] = bias[colBase + tid];

    float acc[2][8][4];
    #pragma unroll
    for (int mi = 0; mi < 2; mi++)
        #pragma unroll
        for (int ni = 0; ni < 8; ni++)
            #pragma unroll
            for (int e = 0; e < 4; e++) acc[mi][ni][e] = 0.0f;

    const int T = Kp / 32;

    // prologue
    stage_A(gsm + OFF_A0, A, lda, rowBase, 0, tid);
    stage_B(sbase + OFF_B,          Bh, Bl, Kp, colBase, 0,  tid);
    CP_COMMIT();
    stage_B(sbase + OFF_B + 16384,  Bh, Bl, Kp, colBase, 32, tid);
    CP_COMMIT();

    // per-lane ldmatrix constants
    const uint32_t aRow = (uint32_t)(wm * 32 + (lane & 15));
    const uint32_t aC0  = (uint32_t)(lane >> 4);
    const uint32_t bRow = (uint32_t)(wn * 64 + (lane & 7));
    const uint32_t bCh  = (uint32_t)(((lane >> 4) & 1) * 4 + ((lane >> 3) & 1));

    for (int t = 0; t < T; t++) {
        CP_WAIT1();          // B_t landed
        __syncthreads();     // A_t stores visible; Bbuf[(t+2)%3] free

        if (t + 2 < T)
            stage_B(sbase + OFF_B + (uint32_t)(((t + 2) % 3) * 16384),
                    Bh, Bl, Kp, colBase, (t + 2) * 32, tid);
        CP_COMMIT();         // unconditional: keeps group arithmetic exact

        // ---- compute tile t ----
        const uint32_t aB = sbase + (uint32_t)((t & 1) ? OFF_A1 : OFF_A0);
        const uint32_t bB = sbase + OFF_B + (uint32_t)((t % 3) * 16384);
        #pragma unroll
        for (int ks = 0; ks < 2; ks++) {
            // packed B fragments: regs 0-1 = Bh frag, 2-3 = Bl frag
            uint32_t bf[8][4];
            #pragma unroll
            for (int ni = 0; ni < 8; ni++) {
                uint32_t r  = bRow + (uint32_t)(ni * 8);
                uint32_t ch = bCh + (uint32_t)(ks * 2);
                ldm_x4(bf[ni], bB + swz((r << 7) + (ch << 4)));
            }
            #pragma unroll
            for (int mi = 0; mi < 2; mi++) {
                uint32_t afh[4], afl[4];
                {
                    uint32_t r  = aRow + (uint32_t)(mi * 16);
                    uint32_t c0 = (uint32_t)(ks * 2) + aC0;
                    ldm_x4(afh, aB + swz((r << 7) + (c0 << 4)));
                    ldm_x4(afl, aB + swz((r << 7) + ((c0 + 4) << 4)));
                }
                #pragma unroll
                for (int ni = 0; ni < 8; ni++) {
                    mma_bf16(acc[mi][ni], afh, &bf[ni][0]);  // Ah*Bh
                    mma_bf16(acc[mi][ni], afh, &bf[ni][2]);  // Ah*Bl
                    mma_bf16(acc[mi][ni], afl, &bf[ni][0]);  // Al*Bh
                }
            }
        }

        // ---- stage A_{t+1} (post-compute; latency covered by co-resident CTA) ----
        if (t + 1 < T)
            stage_A(gsm + ((t + 1) & 1 ? OFF_A1 : OFF_A0),
                    A, lda, rowBase, (t + 1) * 32, tid);
    }

    // ---- epilogue: bias + relu + store ----
    #pragma unroll
    for (int mi = 0; mi < 2; mi++)
        #pragma unroll
        for (int ni = 0; ni < 8; ni++) {
            int m  = rowBase + wm * 32 + mi * 16 + (lane >> 2);
            int nl = wn * 64 + ni * 8 + ((lane & 3) << 1);
            int n  = colBase + nl;
            float b0 = sbias[nl], b1 = sbias[nl + 1];
            float2 v0, v1;
            v0.x = fmaxf(acc[mi][ni][0] + b0, 0.0f);
            v0.y = fmaxf(acc[mi][ni][1] + b1, 0.0f);
            v1.x = fmaxf(acc[mi][ni][2] + b0, 0.0f);
            v1.y = fmaxf(acc[mi][ni][3] + b1, 0.0f);
            *(float2*)(C + (size_t)m * HD + n)       = v0;
            *(float2*)(C + (size_t)(m + 8) * HD + n) = v1;
        }
}

// ---------------- final layer: out = sigmoid(X @ W3^T + b3), W3 [3,256] --------
__global__ void __launch_bounds__(256)
final_kernel(const float* __restrict__ Xin,
             const float* __restrict__ W3,
             const float* __restrict__ b3,
             float* __restrict__ out)
{
    __shared__ float w[3][256];
    __shared__ float bb[3];
    const int tid = threadIdx.x;
    for (int i = tid; i < 768; i += 256) w[i >> 8][i & 255] = W3[i];
    if (tid < 3) bb[tid] = b3[tid];
    __syncthreads();

    const int warp = tid >> 5, lane = tid & 31;
    const int row = blockIdx.x * 8 + warp;
    const float* xr = Xin + (size_t)row * HD;

    float a0 = 0.0f, a1 = 0.0f, a2 = 0.0f;
    #pragma unroll
    for (int i = lane; i < HD; i += 32) {
        float xv = xr[i];
        a0 = fmaf(xv, w[0][i], a0);
        a1 = fmaf(xv, w[1][i], a1);
        a2 = fmaf(xv, w[2][i], a2);
    }
    #pragma unroll
    for (int off = 16; off; off >>= 1) {
        a0 += __shfl_xor_sync(0xffffffffu, a0, off);
        a1 += __shfl_xor_sync(0xffffffffu, a1, off);
        a2 += __shfl_xor_sync(0xffffffffu, a2, off);
    }
    if (lane == 0) {
        out[row * 3 + 0] = 1.0f / (1.0f + expf(-(a0 + bb[0])));
        out[row * 3 + 1] = 1.0f / (1.0f + expf(-(a1 + bb[1])));
        out[row * 3 + 2] = 1.0f / (1.0f + expf(-(a2 + bb[2])));
    }
}

// ---------------- launch --------------------------------------------------------
extern "C" void kernel_launch(void* const* d_in, const int* in_sizes, int n_in,
                              void* d_out, int out_size)
{
    const float* points  = (const float*)d_in[0];
    const float* normals = (const float*)d_in[1];
    const float* fv      = (const float*)d_in[3];
    const float* pp      = (const float*)d_in[5];
    const float* rays    = (const float*)d_in[6];
    const float* ro      = (const float*)d_in[7];
    const float* W0 = (const float*)d_in[8];
    const float* b0 = (const float*)d_in[9];
    const float* W1 = (const float*)d_in[10];
    const float* b1 = (const float*)d_in[11];
    const float* W2 = (const float*)d_in[12];
    const float* b2 = (const float*)d_in[13];
    const float* W3 = (const float*)d_in[14];
    const float* b3 = (const float*)d_in[15];
    float* out = (float*)d_out;

    float *gX, *gh1, *gh2;
    __nv_bfloat16 *w0h, *w0l, *w1h, *w1l, *w2h, *w2l;
    cudaGetSymbolAddress((void**)&gX,  g_X);
    cudaGetSymbolAddress((void**)&gh1, g_h1);
    cudaGetSymbolAddress((void**)&gh2, g_h2);
    cudaGetSymbolAddress((void**)&w0h, g_w0h);
    cudaGetSymbolAddress((void**)&w0l, g_w0l);
    cudaGetSymbolAddress((void**)&w1h, g_w1h);
    cudaGetSymbolAddress((void**)&w1l, g_w1l);
    cudaGetSymbolAddress((void**)&w2h, g_w2h);
    cudaGetSymbolAddress((void**)&w2l, g_w2l);

    cudaFuncSetAttribute(feature_kernel,
                         cudaFuncAttributeMaxDynamicSharedMemorySize, FSMEM);
    cudaFuncSetAttribute(mma_gemm_kernel,
                         cudaFuncAttributeMaxDynamicSharedMemorySize, GSMEM);

    dim3 gg(NQ / BM, HD / BN);   // 192 x 1 (BN=128 -> y=2)

    gridbuild_kernel<<<1, 1024>>>(pp);                                        // 0
    convW_kernel<<<(HD * 512 + 255) / 256, 256>>>(W0, HD, D0, 512, w0h, w0l); // 1
    convW_kernel<<<(HD * HD + 255) / 256, 256>>>(W1, HD, HD, HD, w1h, w1l);   // 2
    feature_kernel<<<NQ / 128, 128, FSMEM>>>(points, normals, rays, ro, fv);  // 3 <- ncu slot
    mma_gemm_kernel<<<gg, 256, GSMEM>>>(gX,  LDX, w0h, w0l, 512, b0, gh1);    // 4
    mma_gemm_kernel<<<gg, 256, GSMEM>>>(gh1, HD,  w1h, w1l, HD,  b1, gh2);    // 5
    convW_kernel<<<(HD * HD + 255) / 256, 256>>>(W2, HD, HD, HD, w2h, w2l);   // 6
    mma_gemm_kernel<<<gg, 256, GSMEM>>>(gh2, HD,  w2h, w2l, HD,  b2, gh1);    // 7
    final_kernel<<<NQ / 8, 256>>>(gh1, W3, b3, out);                          // 8
}

// round 13
// speedup vs baseline: 1.1577x; 1.1577x over previous
#include <cuda_runtime.h>
#include <cuda_bf16.h>
#include <math.h>
#include <cstdint>

#define NQ   24576        // R*S
#define SS   48
#define MP   4096
#define LDX  512          // padded feature stride (D0=511 + 1 zero col)
#define D0   511
#define HD   256

// ---------------- scratch (static device globals; no runtime alloc) ----------
__device__ float g_X [NQ * LDX];   // 50 MB feature matrix (fp32)
__device__ float g_h1[NQ * HD];
__device__ float g_h2[NQ * HD];
__device__ float g_feat[NQ * 16];  // per-query scalars: q3,density,sp3,v3,rd3,dd3
// pre-split weights (bf16 hi/lo), W0 padded K 511 -> 512
__device__ __nv_bfloat16 g_w0h[HD * 512], g_w0l[HD * 512];
__device__ __nv_bfloat16 g_w1h[HD * HD],  g_w1l[HD * HD];
__device__ __nv_bfloat16 g_w2h[HD * HD],  g_w2l[HD * HD];
// spatial grid
__device__ int    g_start[1001];
__device__ float4 g_sorted[MP];    // cell-ordered particles, .w = index bits

// posenc channel tables: j -> (base, C, F, i)
__device__ const int c_base[16] = {0,0,0, 63, 72,72,72, 135,135,135, 198,198,198, 225,225,225};
__device__ const int c_C[16]    = {3,3,3, 1,  3,3,3,    3,3,3,       3,3,3,       3,3,3};
__device__ const int c_F[16]    = {10,10,10, 4, 10,10,10, 10,10,10,  4,4,4,       4,4,4};
__device__ const int c_i[16]    = {0,1,2, 0,  0,1,2,    0,1,2,       0,1,2,       0,1,2};

// ============================ helpers ========================================
__device__ __forceinline__ uint32_t smem_u32(const void* p) {
    uint32_t a;
    asm("{ .reg .u64 t; cvta.to.shared.u64 t, %1; cvt.u32.u64 %0, t; }"
        : "=r"(a) : "l"(p));
    return a;
}
__device__ __forceinline__ void ldm_x4(uint32_t* r, uint32_t addr) {
    asm volatile("ldmatrix.sync.aligned.m8n8.x4.shared.b16 {%0,%1,%2,%3}, [%4];"
        : "=r"(r[0]), "=r"(r[1]), "=r"(r[2]), "=r"(r[3]) : "r"(addr));
}
__device__ __forceinline__ void mma_bf16(float* d, const uint32_t* a, const uint32_t* b) {
    asm volatile("mma.sync.aligned.m16n8k16.row.col.f32.bf16.bf16.f32 "
        "{%0,%1,%2,%3}, {%4,%5,%6,%7}, {%8,%9}, {%0,%1,%2,%3};"
        : "+f"(d[0]), "+f"(d[1]), "+f"(d[2]), "+f"(d[3])
        : "r"(a[0]), "r"(a[1]), "r"(a[2]), "r"(a[3]), "r"(b[0]), "r"(b[1]));
}
#define CP16(dst, src) \
    asm volatile("cp.async.cg.shared.global [%0], [%1], 16;" :: "r"(dst), "l"(src) : "memory")
#define CP_COMMIT() asm volatile("cp.async.commit_group;" ::: "memory")
#define CP_WAIT1()  asm volatile("cp.async.wait_group 1;" ::: "memory")

__device__ __forceinline__ uint32_t swz(uint32_t off) {
    return off ^ ((off >> 3) & 0x70);
}
__device__ __forceinline__ int cell_of(float x, float y, float z) {
    int cx = min(max(__float2int_rd(x * 10.0f), 0), 9);
    int cy = min(max(__float2int_rd(y * 10.0f), 0), 9);
    int cz = min(max(__float2int_rd(z * 10.0f), 0), 9);
    return cx + 10 * cy + 100 * cz;
}

// ---------------- grid build: ONE CTA does count + scan + scatter --------------
__global__ void __launch_bounds__(1024)
gridbuild_kernel(const float* __restrict__ pp)
{
    __shared__ int scnt[1000];
    __shared__ int ssc[1024];
    const int t = threadIdx.x;
    if (t < 1000) scnt[t] = 0;
    __syncthreads();
    for (int i = t; i < MP; i += 1024)
        atomicAdd(&scnt[cell_of(pp[3*i], pp[3*i+1], pp[3*i+2])], 1);
    __syncthreads();
    int v = (t < 1000) ? scnt[t] : 0;
    ssc[t] = v;
    __syncthreads();
    for (int d = 1; d < 1024; d <<= 1) {
        int u = (t >= d) ? ssc[t - d] : 0;
        __syncthreads();
        ssc[t] += u;
        __syncthreads();
    }
    if (t < 1000) { g_start[t] = ssc[t] - v; scnt[t] = ssc[t] - v; }
    if (t == 0)   g_start[1000] = MP;
    __syncthreads();
    for (int i = t; i < MP; i += 1024) {
        float x = pp[3*i], y = pp[3*i+1], z = pp[3*i+2];
        int c = cell_of(x, y, z);
        int pos = atomicAdd(&scnt[c], 1);
        g_sorted[pos] = make_float4(x, y, z, __int_as_float(i));
    }
}

// ---------------- ballquery kernel: scalars only (1 thread / query) ------------
#define BQSMEM (MP * 16 + 4016)

__global__ void __launch_bounds__(128)
ballquery_kernel(const float* __restrict__ points,
                 const float* __restrict__ rays,
                 const float* __restrict__ ro)
{
    extern __shared__ char fsm[];
    float4* spts   = (float4*)fsm;
    int*    sstart = (int*)(fsm + MP * 16);

    const int tid = threadIdx.x;
    for (int i = tid; i < MP;   i += 128) spts[i]   = g_sorted[i];
    for (int i = tid; i < 1001; i += 128) sstart[i] = g_start[i];
    __syncthreads();

    const int gid = blockIdx.x * 128 + tid;
    const float qx = points[3*gid+0], qy = points[3*gid+1], qz = points[3*gid+2];

    const float R2  = (float)(0.1 * 0.1);   // fp64-computed threshold bits
    const float RAD = 0.1f;

    int cand[64];
    int cnt = 0;
    {
        int cx = min(max(__float2int_rd(qx * 10.0f), 0), 9);
        int cy = min(max(__float2int_rd(qy * 10.0f), 0), 9);
        int cz = min(max(__float2int_rd(qz * 10.0f), 0), 9);
        int x0 = max(cx-1,0), x1 = min(cx+1,9);
        int y0 = max(cy-1,0), y1 = min(cy+1,9);
        int z0 = max(cz-1,0), z1 = min(cz+1,9);
        for (int zz = z0; zz <= z1; zz++)
        for (int yy = y0; yy <= y1; yy++)
        for (int xx = x0; xx <= x1; xx++) {
            int c  = xx + 10*yy + 100*zz;
            int s0 = sstart[c], s1 = sstart[c+1];
            for (int i = s0; i < s1; i++) {
                float4 p = spts[i];
                float dx = p.x - qx, dy = p.y - qy, dz = p.z - qz;
                float d2 = dx*dx + dy*dy + dz*dz;
                if (d2 < R2 && cnt < 64)
                    cand[cnt++] = (__float_as_int(p.w) << 12) | i;
            }
        }
    }
    // sort ascending by original index -> first-k-by-index semantics
    for (int i = 1; i < cnt; i++) {
        int v = cand[i], j = i - 1;
        while (j >= 0 && cand[j] > v) { cand[j+1] = cand[j]; j--; }
        cand[j+1] = v;
    }
    const int kk = min(cnt, 16);
    float nx[16], ny[16], nz[16], nd[16];
    for (int k = 0; k < kk; k++) {
        float4 p = spts[cand[k] & 4095];
        float dx = p.x - qx, dy = p.y - qy, dz = p.z - qz;
        nx[k] = p.x; ny[k] = p.y; nz[k] = p.z;
        nd[k] = dx*dx + dy*dy + dz*dz;
    }

    float qn = sqrtf(qx*qx + qy*qy + qz*qz);
    float t0 = qn / RAD;
    float w0 = fmaxf(1.0f - t0*t0*t0, 0.0f);

    float density = 0.0f, smx = 0.0f, smy = 0.0f, smz = 0.0f;
    for (int k = 0; k < 16; k++) {
        if (k < kk) {
            float dn = sqrtf(nd[k]);
            float tt = dn / RAD;
            float w  = fmaxf(1.0f - tt*tt*tt, 0.0f);
            density += w;
            smx += w * nx[k]; smy += w * ny[k]; smz += w * nz[k];
        } else {
            density += w0;
        }
    }

    int   num_nn = 0;
    float sdx = 0.0f, sdy = 0.0f, sdz = 0.0f;
    for (int k = 0; k < kk; k++) {
        if (nd[k] != 0.0f) {
            num_nn++;
            sdx += nx[k] - qx; sdy += ny[k] - qy; sdz += nz[k] - qz;
        }
    }
    float inv = (float)num_nn + 1e-12f;
    float mx = sdx / inv, my = sdy / inv, mz = sdz / inv;
    float vx = 0.0f, vy = 0.0f, vz = 0.0f;
    for (int k = 0; k < kk; k++) {
        if (nd[k] != 0.0f) {
            float ex = (nx[k] - qx) - mx;
            float ey = (ny[k] - qy) - my;
            float ez = (nz[k] - qz) - mz;
            vx += ex*ex; vy += ey*ey; vz += ez*ez;
        }
    }
    vx /= inv; vy /= inv; vz /= inv;

    float dinv = density + 1e-12f;
    float spx = smx / dinv, spy = smy / dinv, spz = smz / dinv;
    float dirx = spx - ro[0], diry = spy - ro[1], dirz = spz - ro[2];
    float dl = sqrtf(dirx*dirx + diry*diry + dirz*dirz);
    dirx /= dl; diry /= dl; dirz /= dl;

    int r = gid / SS;
    float4* o = (float4*)(g_feat + (size_t)gid * 16);
    o[0] = make_float4(qx, qy, qz, density);
    o[1] = make_float4(spx, spy, spz, vx);
    o[2] = make_float4(vy, vz, rays[6*r+3], rays[6*r+4]);
    o[3] = make_float4(rays[6*r+5], dirx, diry, dirz);
}

// ---------------- expand kernel: 16 threads/query, posenc + normals + fv -------
// scalar order in g_feat per query: qx,qy,qz,dens, spx,spy,spz,vx, vy,vz,rdx,rdy,
//                                   rdz,ddx,ddy,ddz
// channel j reads g_feat[q*16 + remap[j]] where remap = identity except the
// layout above packs (v, rd, dd) contiguously: j -> scalar index:
//   j 0..2 -> 0..2 | j3 -> 3 | j4..6 -> 4..6 | j7..9 -> 7..9 | j10..12 -> 10..12
//   j13..15 -> 13..15   (identity!)
__global__ void __launch_bounds__(256)
expand_kernel(const float* __restrict__ normals,
              const float* __restrict__ fv)
{
    const int t = blockIdx.x * 256 + threadIdx.x;   // NQ*16 threads
    const int q = t >> 4, j = t & 15;

    const float val = g_feat[t];
    float* dst = g_X + (size_t)q * LDX;

    const int base = c_base[j];
    const int C    = c_C[j];
    const int F    = c_F[j];
    const int ci   = c_i[j];

    dst[base + ci] = val;
    float s, c;
    sincosf(val, &s, &c);
    int off = base + C + ci;
    for (int f = 0; f < F; f++) {
        dst[off]     = s;
        dst[off + C] = c;
        float ns = 2.0f * s * c;
        float nc = fmaf(-2.0f * s, s, 1.0f);
        s = ns; c = nc;
        off += 2 * C;
    }
    if (j < 3)  dst[252 + j] = normals[3 * q + j];
    if (j == 3) dst[511] = 0.0f;

    // fv block copy: 16 floats per thread -> cols 255+j*16 .. 255+j*16+15
    const float4* src4 = (const float4*)(fv + (size_t)q * 256 + j * 16);
    #pragma unroll
    for (int e = 0; e < 4; e++) {
        float4 v = src4[e];
        int d0 = 255 + j * 16 + e * 4;
        dst[d0 + 0] = v.x; dst[d0 + 1] = v.y;
        dst[d0 + 2] = v.z; dst[d0 + 3] = v.w;
    }
}

// ---------------- weight split: fp32 -> bf16 hi/lo, K padded to Kp -------------
__global__ void __launch_bounds__(256)
convW_kernel(const float* __restrict__ W, int N, int K, int Kp,
             __nv_bfloat16* __restrict__ Wh, __nv_bfloat16* __restrict__ Wl)
{
    int i = blockIdx.x * 256 + threadIdx.x;
    if (i >= N * Kp) return;
    int n = i / Kp, k = i - n * Kp;
    float v = (k < K) ? W[(size_t)n * K + k] : 0.0f;
    __nv_bfloat16 h = __float2bfloat16(v);
    float r = v - __bfloat162float(h);
    Wh[i] = h;
    Wl[i] = __float2bfloat16(r);
}

// ================= warp-mma split-bf16 GEMM (round-9 version, verbatim) =======
#define BM 128
#define BN 128
#define OFF_A0   0
#define OFF_A1   16384
#define OFF_B    32768
#define OFF_BIAS 81920
#define GSMEM    (OFF_BIAS + 512)

__device__ __forceinline__ void cvt8_bf16(const float* a, uint4& hv, uint4& lv)
{
    uint32_t hw[4], lw[4];
    #pragma unroll
    for (int e = 0; e < 4; e++) {
        __nv_bfloat16 h0 = __float2bfloat16(a[2*e]);
        __nv_bfloat16 h1 = __float2bfloat16(a[2*e+1]);
        float r0 = a[2*e]   - __bfloat162float(h0);
        float r1 = a[2*e+1] - __bfloat162float(h1);
        __nv_bfloat16 l0 = __float2bfloat16(r0);
        __nv_bfloat16 l1 = __float2bfloat16(r1);
        hw[e] = (uint32_t)__bfloat16_as_ushort(h0) | ((uint32_t)__bfloat16_as_ushort(h1) << 16);
        lw[e] = (uint32_t)__bfloat16_as_ushort(l0) | ((uint32_t)__bfloat16_as_ushort(l1) << 16);
    }
    hv = make_uint4(hw[0], hw[1], hw[2], hw[3]);
    lv = make_uint4(lw[0], lw[1], lw[2], lw[3]);
}

__device__ __forceinline__ void stage_A(char* dst, const float* __restrict__ A,
                                        int lda, int rowBase, int k0, int tid)
{
    const int arow = tid >> 2, acp = tid & 3;
    #pragma unroll
    for (int i = 0; i < 2; i++) {
        int row = arow + i * 64;
        const float* s = A + (size_t)(rowBase + row) * lda + k0 + acp * 8;
        float av[8];
        *(float4*)&av[0] = *(const float4*)s;
        *(float4*)&av[4] = *(const float4*)(s + 4);
        uint4 hv, lv; cvt8_bf16(av, hv, lv);
        uint32_t off = (uint32_t)(row << 7) + (uint32_t)(acp << 4);
        *(uint4*)(dst + swz(off))      = hv;
        *(uint4*)(dst + swz(off + 64)) = lv;
    }
}

__device__ __forceinline__ void stage_B(uint32_t dst,
                                        const __nv_bfloat16* __restrict__ Bh,
                                        const __nv_bfloat16* __restrict__ Bl,
                                        int ldb, int colBase, int k0, int tid)
{
    #pragma unroll
    for (int i = 0; i < 4; i++) {
        int u = tid + i * 256;
        int r = u >> 3, cu = u & 7;
        const __nv_bfloat16* src = (cu < 4)
            ? Bh + (size_t)(colBase + r) * ldb + k0 + cu * 8
            : Bl + (size_t)(colBase + r) * ldb + k0 + (cu - 4) * 8;
        CP16(dst + swz((uint32_t)(r << 7) + (uint32_t)(cu << 4)), src);
    }
}

__global__ void __launch_bounds__(256, 2)
mma_gemm_kernel(const float* __restrict__ A, int lda,
                const __nv_bfloat16* __restrict__ Bh,
                const __nv_bfloat16* __restrict__ Bl,
                int Kp,
                const float* __restrict__ bias,
                float* __restrict__ C)
{
    extern __shared__ char gsm[];
    const uint32_t sbase = smem_u32(gsm);
    float* sbias = (float*)(gsm + OFF_BIAS);

    const int tid  = threadIdx.x;
    const int wid  = tid >> 5;
    const int lane = tid & 31;
    const int wm   = wid & 3;
    const int wn   = wid >> 2;
    const int rowBase = blockIdx.x * BM;
    const int colBase = blockIdx.y * BN;

    if (tid < 128) sbias[tid] = bias[colBase + tid];

    float acc[2][8][4];
    #pragma unroll
    for (int mi = 0; mi < 2; mi++)
        #pragma unroll
        for (int ni = 0; ni < 8; ni++)
            #pragma unroll
            for (int e = 0; e < 4; e++) acc[mi][ni][e] = 0.0f;

    const int T = Kp / 32;

    stage_A(gsm + OFF_A0, A, lda, rowBase, 0, tid);
    stage_B(sbase + OFF_B,          Bh, Bl, Kp, colBase, 0,  tid);
    CP_COMMIT();
    stage_B(sbase + OFF_B + 16384,  Bh, Bl, Kp, colBase, 32, tid);
    CP_COMMIT();

    const uint32_t aRow = (uint32_t)(wm * 32 + (lane & 15));
    const uint32_t aC0  = (uint32_t)(lane >> 4);
    const uint32_t bRow = (uint32_t)(wn * 64 + (lane & 7));
    const uint32_t bCh  = (uint32_t)(((lane >> 4) & 1) * 4 + ((lane >> 3) & 1));

    for (int t = 0; t < T; t++) {
        CP_WAIT1();
        __syncthreads();

        if (t + 2 < T)
            stage_B(sbase + OFF_B + (uint32_t)(((t + 2) % 3) * 16384),
                    Bh, Bl, Kp, colBase, (t + 2) * 32, tid);
        CP_COMMIT();

        const uint32_t aB = sbase + (uint32_t)((t & 1) ? OFF_A1 : OFF_A0);
        const uint32_t bB = sbase + OFF_B + (uint32_t)((t % 3) * 16384);
        #pragma unroll
        for (int ks = 0; ks < 2; ks++) {
            uint32_t bf[8][4];
            #pragma unroll
            for (int ni = 0; ni < 8; ni++) {
                uint32_t r  = bRow + (uint32_t)(ni * 8);
                uint32_t ch = bCh + (uint32_t)(ks * 2);
                ldm_x4(bf[ni], bB + swz((r << 7) + (ch << 4)));
            }
            #pragma unroll
            for (int mi = 0; mi < 2; mi++) {
                uint32_t afh[4], afl[4];
                {
                    uint32_t r  = aRow + (uint32_t)(mi * 16);
                    uint32_t c0 = (uint32_t)(ks * 2) + aC0;
                    ldm_x4(afh, aB + swz((r << 7) + (c0 << 4)));
                    ldm_x4(afl, aB + swz((r << 7) + ((c0 + 4) << 4)));
                }
                #pragma unroll
                for (int ni = 0; ni < 8; ni++) {
                    mma_bf16(acc[mi][ni], afh, &bf[ni][0]);
                    mma_bf16(acc[mi][ni], afh, &bf[ni][2]);
                    mma_bf16(acc[mi][ni], afl, &bf[ni][0]);
                }
            }
        }

        if (t + 1 < T)
            stage_A(gsm + ((t + 1) & 1 ? OFF_A1 : OFF_A0),
                    A, lda, rowBase, (t + 1) * 32, tid);
    }

    #pragma unroll
    for (int mi = 0; mi < 2; mi++)
        #pragma unroll
        for (int ni = 0; ni < 8; ni++) {
            int m  = rowBase + wm * 32 + mi * 16 + (lane >> 2);
            int nl = wn * 64 + ni * 8 + ((lane & 3) << 1);
            int n  = colBase + nl;
            float b0 = sbias[nl], b1 = sbias[nl + 1];
            float2 v0, v1;
            v0.x = fmaxf(acc[mi][ni][0] + b0, 0.0f);
            v0.y = fmaxf(acc[mi][ni][1] + b1, 0.0f);
            v1.x = fmaxf(acc[mi][ni][2] + b0, 0.0f);
            v1.y = fmaxf(acc[mi][ni][3] + b1, 0.0f);
            *(float2*)(C + (size_t)m * HD + n)       = v0;
            *(float2*)(C + (size_t)(m + 8) * HD + n) = v1;
        }
}

// ---------------- final layer: out = sigmoid(X @ W3^T + b3), W3 [3,256] --------
__global__ void __launch_bounds__(256)
final_kernel(const float* __restrict__ Xin,
             const float* __restrict__ W3,
             const float* __restrict__ b3,
             float* __restrict__ out)
{
    __shared__ float w[3][256];
    __shared__ float bb[3];
    const int tid = threadIdx.x;
    for (int i = tid; i < 768; i += 256) w[i >> 8][i & 255] = W3[i];
    if (tid < 3) bb[tid] = b3[tid];
    __syncthreads();

    const int warp = tid >> 5, lane = tid & 31;
    const int row = blockIdx.x * 8 + warp;
    const float* xr = Xin + (size_t)row * HD;

    float a0 = 0.0f, a1 = 0.0f, a2 = 0.0f;
    #pragma unroll
    for (int i = lane; i < HD; i += 32) {
        float xv = xr[i];
        a0 = fmaf(xv, w[0][i], a0);
        a1 = fmaf(xv, w[1][i], a1);
        a2 = fmaf(xv, w[2][i], a2);
    }
    #pragma unroll
    for (int off = 16; off; off >>= 1) {
        a0 += __shfl_xor_sync(0xffffffffu, a0, off);
        a1 += __shfl_xor_sync(0xffffffffu, a1, off);
        a2 += __shfl_xor_sync(0xffffffffu, a2, off);
    }
    if (lane == 0) {
        out[row * 3 + 0] = 1.0f / (1.0f + expf(-(a0 + bb[0])));
        out[row * 3 + 1] = 1.0f / (1.0f + expf(-(a1 + bb[1])));
        out[row * 3 + 2] = 1.0f / (1.0f + expf(-(a2 + bb[2])));
    }
}

// ---------------- launch --------------------------------------------------------
extern "C" void kernel_launch(void* const* d_in, const int* in_sizes, int n_in,
                              void* d_out, int out_size)
{
    const float* points  = (const float*)d_in[0];
    const float* normals = (const float*)d_in[1];
    const float* fv      = (const float*)d_in[3];
    const float* pp      = (const float*)d_in[5];
    const float* rays    = (const float*)d_in[6];
    const float* ro      = (const float*)d_in[7];
    const float* W0 = (const float*)d_in[8];
    const float* b0 = (const float*)d_in[9];
    const float* W1 = (const float*)d_in[10];
    const float* b1 = (const float*)d_in[11];
    const float* W2 = (const float*)d_in[12];
    const float* b2 = (const float*)d_in[13];
    const float* W3 = (const float*)d_in[14];
    const float* b3 = (const float*)d_in[15];
    float* out = (float*)d_out;

    float *gX, *gh1, *gh2;
    __nv_bfloat16 *w0h, *w0l, *w1h, *w1l, *w2h, *w2l;
    cudaGetSymbolAddress((void**)&gX,  g_X);
    cudaGetSymbolAddress((void**)&gh1, g_h1);
    cudaGetSymbolAddress((void**)&gh2, g_h2);
    cudaGetSymbolAddress((void**)&w0h, g_w0h);
    cudaGetSymbolAddress((void**)&w0l, g_w0l);
    cudaGetSymbolAddress((void**)&w1h, g_w1h);
    cudaGetSymbolAddress((void**)&w1l, g_w1l);
    cudaGetSymbolAddress((void**)&w2h, g_w2h);
    cudaGetSymbolAddress((void**)&w2l, g_w2l);

    cudaFuncSetAttribute(ballquery_kernel,
                         cudaFuncAttributeMaxDynamicSharedMemorySize, BQSMEM);
    cudaFuncSetAttribute(mma_gemm_kernel,
                         cudaFuncAttributeMaxDynamicSharedMemorySize, GSMEM);

    dim3 gg(NQ / BM, HD / BN);

    gridbuild_kernel<<<1, 1024>>>(pp);                                        // 0
    convW_kernel<<<(HD * 512 + 255) / 256, 256>>>(W0, HD, D0, 512, w0h, w0l); // 1
    convW_kernel<<<(HD * HD + 255) / 256, 256>>>(W1, HD, HD, HD, w1h, w1l);   // 2
    ballquery_kernel<<<NQ / 128, 128, BQSMEM>>>(points, rays, ro);            // 3 <- ncu slot
    expand_kernel<<<(NQ * 16) / 256, 256>>>(normals, fv);                     // 4
    mma_gemm_kernel<<<gg, 256, GSMEM>>>(gX,  LDX, w0h, w0l, 512, b0, gh1);    // 5
    mma_gemm_kernel<<<gg, 256, GSMEM>>>(gh1, HD,  w1h, w1l, HD,  b1, gh2);    // 6
    convW_kernel<<<(HD * HD + 255) / 256, 256>>>(W2, HD, HD, HD, w2h, w2l);   // 7
    mma_gemm_kernel<<<gg, 256, GSMEM>>>(gh2, HD,  w2h, w2l, HD,  b2, gh1);    // 8
    final_kernel<<<NQ / 8, 256>>>(gh1, W3, b3, out);                          // 9
}

// round 14
// speedup vs baseline: 1.2081x; 1.0435x over previous
#include <cuda_runtime.h>
#include <cuda_bf16.h>
#include <math.h>
#include <cstdint>

#define NQ   24576        // R*S
#define SS   48
#define MP   4096
#define LDX  512          // padded feature stride (D0=511 + 1 zero col)
#define D0   511
#define HD   256

// ---------------- scratch (static device globals; no runtime alloc) ----------
__device__ float g_X [NQ * LDX];   // 50 MB feature matrix (fp32)
__device__ float g_h1[NQ * HD];
__device__ float g_h2[NQ * HD];
__device__ float g_feat[NQ * 16];  // per-query scalars: q3,density,sp3,v3,rd3,dd3
// pre-split weights (bf16 hi/lo), W0 padded K 511 -> 512
__device__ __nv_bfloat16 g_w0h[HD * 512], g_w0l[HD * 512];
__device__ __nv_bfloat16 g_w1h[HD * HD],  g_w1l[HD * HD];
__device__ __nv_bfloat16 g_w2h[HD * HD],  g_w2l[HD * HD];
// spatial grid
__device__ int    g_start[1001];
__device__ float4 g_sorted[MP];    // cell-ordered particles, .w = index bits

// posenc channel tables: j -> (base, C, F, i)
__device__ const int c_base[16] = {0,0,0, 63, 72,72,72, 135,135,135, 198,198,198, 225,225,225};
__device__ const int c_C[16]    = {3,3,3, 1,  3,3,3,    3,3,3,       3,3,3,       3,3,3};
__device__ const int c_F[16]    = {10,10,10, 4, 10,10,10, 10,10,10,  4,4,4,       4,4,4};
__device__ const int c_i[16]    = {0,1,2, 0,  0,1,2,    0,1,2,       0,1,2,       0,1,2};

// ============================ helpers ========================================
__device__ __forceinline__ uint32_t smem_u32(const void* p) {
    uint32_t a;
    asm("{ .reg .u64 t; cvta.to.shared.u64 t, %1; cvt.u32.u64 %0, t; }"
        : "=r"(a) : "l"(p));
    return a;
}
__device__ __forceinline__ void ldm_x4(uint32_t* r, uint32_t addr) {
    asm volatile("ldmatrix.sync.aligned.m8n8.x4.shared.b16 {%0,%1,%2,%3}, [%4];"
        : "=r"(r[0]), "=r"(r[1]), "=r"(r[2]), "=r"(r[3]) : "r"(addr));
}
__device__ __forceinline__ void mma_bf16(float* d, const uint32_t* a, const uint32_t* b) {
    asm volatile("mma.sync.aligned.m16n8k16.row.col.f32.bf16.bf16.f32 "
        "{%0,%1,%2,%3}, {%4,%5,%6,%7}, {%8,%9}, {%0,%1,%2,%3};"
        : "+f"(d[0]), "+f"(d[1]), "+f"(d[2]), "+f"(d[3])
        : "r"(a[0]), "r"(a[1]), "r"(a[2]), "r"(a[3]), "r"(b[0]), "r"(b[1]));
}
#define CP16(dst, src) \
    asm volatile("cp.async.cg.shared.global [%0], [%1], 16;" :: "r"(dst), "l"(src) : "memory")
#define CP_COMMIT() asm volatile("cp.async.commit_group;" ::: "memory")
#define CP_WAIT1()  asm volatile("cp.async.wait_group 1;" ::: "memory")

__device__ __forceinline__ uint32_t swz(uint32_t off) {
    return off ^ ((off >> 3) & 0x70);
}
__device__ __forceinline__ int cell_of(float x, float y, float z) {
    int cx = min(max(__float2int_rd(x * 10.0f), 0), 9);
    int cy = min(max(__float2int_rd(y * 10.0f), 0), 9);
    int cz = min(max(__float2int_rd(z * 10.0f), 0), 9);
    return cx + 10 * cy + 100 * cz;
}

// ---------------- grid build: ONE CTA does count + scan + scatter --------------
__global__ void __launch_bounds__(1024)
gridbuild_kernel(const float* __restrict__ pp)
{
    __shared__ int scnt[1000];
    __shared__ int ssc[1024];
    const int t = threadIdx.x;
    if (t < 1000) scnt[t] = 0;
    __syncthreads();
    for (int i = t; i < MP; i += 1024)
        atomicAdd(&scnt[cell_of(pp[3*i], pp[3*i+1], pp[3*i+2])], 1);
    __syncthreads();
    int v = (t < 1000) ? scnt[t] : 0;
    ssc[t] = v;
    __syncthreads();
    for (int d = 1; d < 1024; d <<= 1) {
        int u = (t >= d) ? ssc[t - d] : 0;
        __syncthreads();
        ssc[t] += u;
        __syncthreads();
    }
    if (t < 1000) { g_start[t] = ssc[t] - v; scnt[t] = ssc[t] - v; }
    if (t == 0)   g_start[1000] = MP;
    __syncthreads();
    for (int i = t; i < MP; i += 1024) {
        float x = pp[3*i], y = pp[3*i+1], z = pp[3*i+2];
        int c = cell_of(x, y, z);
        int pos = atomicAdd(&scnt[c], 1);
        g_sorted[pos] = make_float4(x, y, z, __int_as_float(i));
    }
}

// ---------------- ballquery kernel: 4 threads / query --------------------------
// Each of 4 sub-threads scans cells (round-robin by enumeration order), builds a
// sorted candidate list (key = idx<<12 | slot) in smem; sub-thread 0 merges the
// 4 sorted lists taking the first 16 by key, then computes the statistics.
#define QPB 64            // queries per block (256 threads)
#define LCAP 32           // per-sub-thread candidate cap

__global__ void __launch_bounds__(256)
ballquery_kernel(const float* __restrict__ points,
                 const float* __restrict__ rays,
                 const float* __restrict__ ro)
{
    __shared__ int sstart[1001];
    __shared__ int sl[256 * (LCAP + 1)];    // stride 33: conflict-free
    __shared__ int sc[256];

    const int tid = threadIdx.x;
    for (int i = tid; i < 1001; i += 256) sstart[i] = g_start[i];
    __syncthreads();

    const int ql  = tid >> 2;               // local query 0..63
    const int j   = tid & 3;                // sub-thread 0..3
    const int gid = blockIdx.x * QPB + ql;

    const float qx = points[3*gid+0], qy = points[3*gid+1], qz = points[3*gid+2];

    const float R2  = (float)(0.1 * 0.1);   // fp64-computed threshold bits
    const float RAD = 0.1f;

    int* myrow = sl + tid * (LCAP + 1);
    int cnt = 0;
    {
        int cx = min(max(__float2int_rd(qx * 10.0f), 0), 9);
        int cy = min(max(__float2int_rd(qy * 10.0f), 0), 9);
        int cz = min(max(__float2int_rd(qz * 10.0f), 0), 9);
        int x0 = max(cx-1,0), x1 = min(cx+1,9);
        int y0 = max(cy-1,0), y1 = min(cy+1,9);
        int z0 = max(cz-1,0), z1 = min(cz+1,9);
        int ci = 0;
        for (int zz = z0; zz <= z1; zz++)
        for (int yy = y0; yy <= y1; yy++)
        for (int xx = x0; xx <= x1; xx++) {
            if ((ci++ & 3) != j) continue;
            int c  = xx + 10*yy + 100*zz;
            int s0 = sstart[c], s1 = sstart[c+1];
            for (int i = s0; i < s1; i++) {
                float4 p = g_sorted[i];
                float dx = p.x - qx, dy = p.y - qy, dz = p.z - qz;
                float d2 = dx*dx + dy*dy + dz*dz;
                if (d2 < R2 && cnt < LCAP) {
                    int key = (__float_as_int(p.w) << 12) | i;
                    // sorted insert (ascending by key)
                    int pos = cnt - 1;
                    while (pos >= 0 && myrow[pos] > key) {
                        myrow[pos + 1] = myrow[pos];
                        pos--;
                    }
                    myrow[pos + 1] = key;
                    cnt++;
                }
            }
        }
    }
    sc[tid] = cnt;
    __syncthreads();

    if (j != 0) return;

    // ---- 4-way merge of sorted lists, first 16 by key ----
    int keys[16];
    int kk = 0;
    {
        int h0 = 0, h1 = 0, h2 = 0, h3 = 0;
        const int* r0 = sl + (tid + 0) * (LCAP + 1);
        const int* r1 = sl + (tid + 1) * (LCAP + 1);
        const int* r2 = sl + (tid + 2) * (LCAP + 1);
        const int* r3 = sl + (tid + 3) * (LCAP + 1);
        const int c0 = sc[tid], c1 = sc[tid+1], c2 = sc[tid+2], c3 = sc[tid+3];
        while (kk < 16) {
            int best = 0x7fffffff, bj = -1;
            int v;
            if (h0 < c0) { v = r0[h0]; if (v < best) { best = v; bj = 0; } }
            if (h1 < c1) { v = r1[h1]; if (v < best) { best = v; bj = 1; } }
            if (h2 < c2) { v = r2[h2]; if (v < best) { best = v; bj = 2; } }
            if (h3 < c3) { v = r3[h3]; if (v < best) { best = v; bj = 3; } }
            if (bj < 0) break;
            keys[kk++] = best;
            if (bj == 0) h0++; else if (bj == 1) h1++;
            else if (bj == 2) h2++; else h3++;
        }
    }

    float nx[16], ny[16], nz[16], nd[16];
    for (int k = 0; k < kk; k++) {
        float4 p = g_sorted[keys[k] & 4095];
        float dx = p.x - qx, dy = p.y - qy, dz = p.z - qz;
        nx[k] = p.x; ny[k] = p.y; nz[k] = p.z;
        nd[k] = dx*dx + dy*dy + dz*dz;
    }

    float qn = sqrtf(qx*qx + qy*qy + qz*qz);
    float t0 = qn / RAD;
    float w0 = fmaxf(1.0f - t0*t0*t0, 0.0f);

    float density = 0.0f, smx = 0.0f, smy = 0.0f, smz = 0.0f;
    for (int k = 0; k < 16; k++) {
        if (k < kk) {
            float dn = sqrtf(nd[k]);
            float tt = dn / RAD;
            float w  = fmaxf(1.0f - tt*tt*tt, 0.0f);
            density += w;
            smx += w * nx[k]; smy += w * ny[k]; smz += w * nz[k];
        } else {
            density += w0;
        }
    }

    int   num_nn = 0;
    float sdx = 0.0f, sdy = 0.0f, sdz = 0.0f;
    for (int k = 0; k < kk; k++) {
        if (nd[k] != 0.0f) {
            num_nn++;
            sdx += nx[k] - qx; sdy += ny[k] - qy; sdz += nz[k] - qz;
        }
    }
    float inv = (float)num_nn + 1e-12f;
    float mx = sdx / inv, my = sdy / inv, mz = sdz / inv;
    float vx = 0.0f, vy = 0.0f, vz = 0.0f;
    for (int k = 0; k < kk; k++) {
        if (nd[k] != 0.0f) {
            float ex = (nx[k] - qx) - mx;
            float ey = (ny[k] - qy) - my;
            float ez = (nz[k] - qz) - mz;
            vx += ex*ex; vy += ey*ey; vz += ez*ez;
        }
    }
    vx /= inv; vy /= inv; vz /= inv;

    float dinv = density + 1e-12f;
    float spx = smx / dinv, spy = smy / dinv, spz = smz / dinv;
    float dirx = spx - ro[0], diry = spy - ro[1], dirz = spz - ro[2];
    float dl = sqrtf(dirx*dirx + diry*diry + dirz*dirz);
    dirx /= dl; diry /= dl; dirz /= dl;

    int r = gid / SS;
    float4* o = (float4*)(g_feat + (size_t)gid * 16);
    o[0] = make_float4(qx, qy, qz, density);
    o[1] = make_float4(spx, spy, spz, vx);
    o[2] = make_float4(vy, vz, rays[6*r+3], rays[6*r+4]);
    o[3] = make_float4(rays[6*r+5], dirx, diry, dirz);
}

// ---------------- expand kernel: 16 threads/query, posenc + normals + fv -------
__global__ void __launch_bounds__(256)
expand_kernel(const float* __restrict__ normals,
              const float* __restrict__ fv)
{
    const int t = blockIdx.x * 256 + threadIdx.x;   // NQ*16 threads
    const int q = t >> 4, j = t & 15;

    const float val = g_feat[t];
    float* dst = g_X + (size_t)q * LDX;

    const int base = c_base[j];
    const int C    = c_C[j];
    const int F    = c_F[j];
    const int ci   = c_i[j];

    dst[base + ci] = val;
    float s, c;
    sincosf(val, &s, &c);
    int off = base + C + ci;
    for (int f = 0; f < F; f++) {
        dst[off]     = s;
        dst[off + C] = c;
        float ns = 2.0f * s * c;
        float nc = fmaf(-2.0f * s, s, 1.0f);
        s = ns; c = nc;
        off += 2 * C;
    }
    if (j < 3)  dst[252 + j] = normals[3 * q + j];
    if (j == 3) dst[511] = 0.0f;

    // fv block copy: 16 floats per thread -> cols 255+j*16 .. 255+j*16+15
    const float4* src4 = (const float4*)(fv + (size_t)q * 256 + j * 16);
    #pragma unroll
    for (int e = 0; e < 4; e++) {
        float4 v = src4[e];
        int d0 = 255 + j * 16 + e * 4;
        dst[d0 + 0] = v.x; dst[d0 + 1] = v.y;
        dst[d0 + 2] = v.z; dst[d0 + 3] = v.w;
    }
}

// ---------------- weight split: fp32 -> bf16 hi/lo, K padded to Kp -------------
__global__ void __launch_bounds__(256)
convW_kernel(const float* __restrict__ W, int N, int K, int Kp,
             __nv_bfloat16* __restrict__ Wh, __nv_bfloat16* __restrict__ Wl)
{
    int i = blockIdx.x * 256 + threadIdx.x;
    if (i >= N * Kp) return;
    int n = i / Kp, k = i - n * Kp;
    float v = (k < K) ? W[(size_t)n * K + k] : 0.0f;
    __nv_bfloat16 h = __float2bfloat16(v);
    float r = v - __bfloat162float(h);
    Wh[i] = h;
    Wl[i] = __float2bfloat16(r);
}

// ================= warp-mma split-bf16 GEMM (round-9 version, verbatim) =======
#define BM 128
#define BN 128
#define OFF_A0   0
#define OFF_A1   16384
#define OFF_B    32768
#define OFF_BIAS 81920
#define GSMEM    (OFF_BIAS + 512)

__device__ __forceinline__ void cvt8_bf16(const float* a, uint4& hv, uint4& lv)
{
    uint32_t hw[4], lw[4];
    #pragma unroll
    for (int e = 0; e < 4; e++) {
        __nv_bfloat16 h0 = __float2bfloat16(a[2*e]);
        __nv_bfloat16 h1 = __float2bfloat16(a[2*e+1]);
        float r0 = a[2*e]   - __bfloat162float(h0);
        float r1 = a[2*e+1] - __bfloat162float(h1);
        __nv_bfloat16 l0 = __float2bfloat16(r0);
        __nv_bfloat16 l1 = __float2bfloat16(r1);
        hw[e] = (uint32_t)__bfloat16_as_ushort(h0) | ((uint32_t)__bfloat16_as_ushort(h1) << 16);
        lw[e] = (uint32_t)__bfloat16_as_ushort(l0) | ((uint32_t)__bfloat16_as_ushort(l1) << 16);
    }
    hv = make_uint4(hw[0], hw[1], hw[2], hw[3]);
    lv = make_uint4(lw[0], lw[1], lw[2], lw[3]);
}

__device__ __forceinline__ void stage_A(char* dst, const float* __restrict__ A,
                                        int lda, int rowBase, int k0, int tid)
{
    const int arow = tid >> 2, acp = tid & 3;
    #pragma unroll
    for (int i = 0; i < 2; i++) {
        int row = arow + i * 64;
        const float* s = A + (size_t)(rowBase + row) * lda + k0 + acp * 8;
        float av[8];
        *(float4*)&av[0] = *(const float4*)s;
        *(float4*)&av[4] = *(const float4*)(s + 4);
        uint4 hv, lv; cvt8_bf16(av, hv, lv);
        uint32_t off = (uint32_t)(row << 7) + (uint32_t)(acp << 4);
        *(uint4*)(dst + swz(off))      = hv;
        *(uint4*)(dst + swz(off + 64)) = lv;
    }
}

__device__ __forceinline__ void stage_B(uint32_t dst,
                                        const __nv_bfloat16* __restrict__ Bh,
                                        const __nv_bfloat16* __restrict__ Bl,
                                        int ldb, int colBase, int k0, int tid)
{
    #pragma unroll
    for (int i = 0; i < 4; i++) {
        int u = tid + i * 256;
        int r = u >> 3, cu = u & 7;
        const __nv_bfloat16* src = (cu < 4)
            ? Bh + (size_t)(colBase + r) * ldb + k0 + cu * 8
            : Bl + (size_t)(colBase + r) * ldb + k0 + (cu - 4) * 8;
        CP16(dst + swz((uint32_t)(r << 7) + (uint32_t)(cu << 4)), src);
    }
}

__global__ void __launch_bounds__(256, 2)
mma_gemm_kernel(const float* __restrict__ A, int lda,
                const __nv_bfloat16* __restrict__ Bh,
                const __nv_bfloat16* __restrict__ Bl,
                int Kp,
                const float* __restrict__ bias,
                float* __restrict__ C)
{
    extern __shared__ char gsm[];
    const uint32_t sbase = smem_u32(gsm);
    float* sbias = (float*)(gsm + OFF_BIAS);

    const int tid  = threadIdx.x;
    const int wid  = tid >> 5;
    const int lane = tid & 31;
    const int wm   = wid & 3;
    const int wn   = wid >> 2;
    const int rowBase = blockIdx.x * BM;
    const int colBase = blockIdx.y * BN;

    if (tid < 128) sbias[tid] = bias[colBase + tid];

    float acc[2][8][4];
    #pragma unroll
    for (int mi = 0; mi < 2; mi++)
        #pragma unroll
        for (int ni = 0; ni < 8; ni++)
            #pragma unroll
            for (int e = 0; e < 4; e++) acc[mi][ni][e] = 0.0f;

    const int T = Kp / 32;

    stage_A(gsm + OFF_A0, A, lda, rowBase, 0, tid);
    stage_B(sbase + OFF_B,          Bh, Bl, Kp, colBase, 0,  tid);
    CP_COMMIT();
    stage_B(sbase + OFF_B + 16384,  Bh, Bl, Kp, colBase, 32, tid);
    CP_COMMIT();

    const uint32_t aRow = (uint32_t)(wm * 32 + (lane & 15));
    const uint32_t aC0  = (uint32_t)(lane >> 4);
    const uint32_t bRow = (uint32_t)(wn * 64 + (lane & 7));
    const uint32_t bCh  = (uint32_t)(((lane >> 4) & 1) * 4 + ((lane >> 3) & 1));

    for (int t = 0; t < T; t++) {
        CP_WAIT1();
        __syncthreads();

        if (t + 2 < T)
            stage_B(sbase + OFF_B + (uint32_t)(((t + 2) % 3) * 16384),
                    Bh, Bl, Kp, colBase, (t + 2) * 32, tid);
        CP_COMMIT();

        const uint32_t aB = sbase + (uint32_t)((t & 1) ? OFF_A1 : OFF_A0);
        const uint32_t bB = sbase + OFF_B + (uint32_t)((t % 3) * 16384);
        #pragma unroll
        for (int ks = 0; ks < 2; ks++) {
            uint32_t bf[8][4];
            #pragma unroll
            for (int ni = 0; ni < 8; ni++) {
                uint32_t r  = bRow + (uint32_t)(ni * 8);
                uint32_t ch = bCh + (uint32_t)(ks * 2);
                ldm_x4(bf[ni], bB + swz((r << 7) + (ch << 4)));
            }
            #pragma unroll
            for (int mi = 0; mi < 2; mi++) {
                uint32_t afh[4], afl[4];
                {
                    uint32_t r  = aRow + (uint32_t)(mi * 16);
                    uint32_t c0 = (uint32_t)(ks * 2) + aC0;
                    ldm_x4(afh, aB + swz((r << 7) + (c0 << 4)));
                    ldm_x4(afl, aB + swz((r << 7) + ((c0 + 4) << 4)));
                }
                #pragma unroll
                for (int ni = 0; ni < 8; ni++) {
                    mma_bf16(acc[mi][ni], afh, &bf[ni][0]);
                    mma_bf16(acc[mi][ni], afh, &bf[ni][2]);
                    mma_bf16(acc[mi][ni], afl, &bf[ni][0]);
                }
            }
        }

        if (t + 1 < T)
            stage_A(gsm + ((t + 1) & 1 ? OFF_A1 : OFF_A0),
                    A, lda, rowBase, (t + 1) * 32, tid);
    }

    #pragma unroll
    for (int mi = 0; mi < 2; mi++)
        #pragma unroll
        for (int ni = 0; ni < 8; ni++) {
            int m  = rowBase + wm * 32 + mi * 16 + (lane >> 2);
            int nl = wn * 64 + ni * 8 + ((lane & 3) << 1);
            int n  = colBase + nl;
            float b0 = sbias[nl], b1 = sbias[nl + 1];
            float2 v0, v1;
            v0.x = fmaxf(acc[mi][ni][0] + b0, 0.0f);
            v0.y = fmaxf(acc[mi][ni][1] + b1, 0.0f);
            v1.x = fmaxf(acc[mi][ni][2] + b0, 0.0f);
            v1.y = fmaxf(acc[mi][ni][3] + b1, 0.0f);
            *(float2*)(C + (size_t)m * HD + n)       = v0;
            *(float2*)(C + (size_t)(m + 8) * HD + n) = v1;
        }
}

// ---------------- final layer: out = sigmoid(X @ W3^T + b3), W3 [3,256] --------
__global__ void __launch_bounds__(256)
final_kernel(const float* __restrict__ Xin,
             const float* __restrict__ W3,
             const float* __restrict__ b3,
             float* __restrict__ out)
{
    __shared__ float w[3][256];
    __shared__ float bb[3];
    const int tid = threadIdx.x;
    for (int i = tid; i < 768; i += 256) w[i >> 8][i & 255] = W3[i];
    if (tid < 3) bb[tid] = b3[tid];
    __syncthreads();

    const int warp = tid >> 5, lane = tid & 31;
    const int row = blockIdx.x * 8 + warp;
    const float* xr = Xin + (size_t)row * HD;

    float a0 = 0.0f, a1 = 0.0f, a2 = 0.0f;
    #pragma unroll
    for (int i = lane; i < HD; i += 32) {
        float xv = xr[i];
        a0 = fmaf(xv, w[0][i], a0);
        a1 = fmaf(xv, w[1][i], a1);
        a2 = fmaf(xv, w[2][i], a2);
    }
    #pragma unroll
    for (int off = 16; off; off >>= 1) {
        a0 += __shfl_xor_sync(0xffffffffu, a0, off);
        a1 += __shfl_xor_sync(0xffffffffu, a1, off);
        a2 += __shfl_xor_sync(0xffffffffu, a2, off);
    }
    if (lane == 0) {
        out[row * 3 + 0] = 1.0f / (1.0f + expf(-(a0 + bb[0])));
        out[row * 3 + 1] = 1.0f / (1.0f + expf(-(a1 + bb[1])));
        out[row * 3 + 2] = 1.0f / (1.0f + expf(-(a2 + bb[2])));
    }
}

// ---------------- launch --------------------------------------------------------
extern "C" void kernel_launch(void* const* d_in, const int* in_sizes, int n_in,
                              void* d_out, int out_size)
{
    const float* points  = (const float*)d_in[0];
    const float* normals = (const float*)d_in[1];
    const float* fv      = (const float*)d_in[3];
    const float* pp      = (const float*)d_in[5];
    const float* rays    = (const float*)d_in[6];
    const float* ro      = (const float*)d_in[7];
    const float* W0 = (const float*)d_in[8];
    const float* b0 = (const float*)d_in[9];
    const float* W1 = (const float*)d_in[10];
    const float* b1 = (const float*)d_in[11];
    const float* W2 = (const float*)d_in[12];
    const float* b2 = (const float*)d_in[13];
    const float* W3 = (const float*)d_in[14];
    const float* b3 = (const float*)d_in[15];
    float* out = (float*)d_out;

    float *gX, *gh1, *gh2;
    __nv_bfloat16 *w0h, *w0l, *w1h, *w1l, *w2h, *w2l;
    cudaGetSymbolAddress((void**)&gX,  g_X);
    cudaGetSymbolAddress((void**)&gh1, g_h1);
    cudaGetSymbolAddress((void**)&gh2, g_h2);
    cudaGetSymbolAddress((void**)&w0h, g_w0h);
    cudaGetSymbolAddress((void**)&w0l, g_w0l);
    cudaGetSymbolAddress((void**)&w1h, g_w1h);
    cudaGetSymbolAddress((void**)&w1l, g_w1l);
    cudaGetSymbolAddress((void**)&w2h, g_w2h);
    cudaGetSymbolAddress((void**)&w2l, g_w2l);

    cudaFuncSetAttribute(mma_gemm_kernel,
                         cudaFuncAttributeMaxDynamicSharedMemorySize, GSMEM);

    dim3 gg(NQ / BM, HD / BN);

    gridbuild_kernel<<<1, 1024>>>(pp);                                        // 0
    convW_kernel<<<(HD * 512 + 255) / 256, 256>>>(W0, HD, D0, 512, w0h, w0l); // 1
    convW_kernel<<<(HD * HD + 255) / 256, 256>>>(W1, HD, HD, HD, w1h, w1l);   // 2
    ballquery_kernel<<<NQ / QPB, 256>>>(points, rays, ro);                    // 3 <- ncu slot
    expand_kernel<<<(NQ * 16) / 256, 256>>>(normals, fv);                     // 4
    mma_gemm_kernel<<<gg, 256, GSMEM>>>(gX,  LDX, w0h, w0l, 512, b0, gh1);    // 5
    mma_gemm_kernel<<<gg, 256, GSMEM>>>(gh1, HD,  w1h, w1l, HD,  b1, gh2);    // 6
    convW_kernel<<<(HD * HD + 255) / 256, 256>>>(W2, HD, HD, HD, w2h, w2l);   // 7
    mma_gemm_kernel<<<gg, 256, GSMEM>>>(gh2, HD,  w2h, w2l, HD,  b2, gh1);    // 8
    final_kernel<<<NQ / 8, 256>>>(gh1, W3, b3, out);                          // 9
}